// round 10
// baseline (speedup 1.0000x reference)
#include <cuda_runtime.h>
#include <cuda_bf16.h>
#include <math.h>
#include <stdint.h>

#define VIEWS 32
#define KNN 5
#define DIM 1024
#define MAXROWS 16384
#define IMG_ELEMS (3*34*34)   // 3468
#define NCHUNK 16             // K chunks of 64 bf16 (128B)
#define NSTAGE 3

// ---------------- static device scratch (no allocation allowed) ----------------
__device__ float g_F [(size_t)MAXROWS * DIM];                       // conv features (fp32)
__device__ __align__(1024) unsigned char g_Ahi[(size_t)NCHUNK * MAXROWS * 128];  // 32MB
__device__ __align__(1024) unsigned char g_Alo[(size_t)NCHUNK * MAXROWS * 128];  // 32MB
__device__ __align__(1024) unsigned char g_Bhi[(size_t)NCHUNK * DIM * 128];      // 2MB
__device__ __align__(1024) unsigned char g_Blo[(size_t)NCHUNK * DIM * 128];      // 2MB
__device__ int   g_idx[VIEWS * KNN];
__device__ float g_e  [VIEWS * KNN];
__device__ float g_sum  [DIM];
__device__ float g_sumsq[DIM];
__device__ float g_scale[DIM];
__device__ float g_shift[DIM];

// ---------------- PTX helpers (portable to plain sm_103 target) ----------------
__device__ __forceinline__ uint32_t smem_u32(const void* p) {
    uint32_t a;
    asm("{ .reg .u64 t; cvta.to.shared.u64 t, %1; cvt.u32.u64 %0, t; }" : "=r"(a) : "l"(p));
    return a;
}

#define MBARRIER_INIT(addr, cnt) \
    asm volatile("mbarrier.init.shared.b64 [%0], %1;" :: "r"((uint32_t)(addr)), "r"((uint32_t)(cnt)) : "memory")

#define MBARRIER_EXPECT_TX(addr, bytes) \
    asm volatile("mbarrier.arrive.expect_tx.shared.b64 _, [%0], %1;" :: "r"((uint32_t)(addr)), "r"((uint32_t)(bytes)) : "memory")

#define MBARRIER_WAIT_PARITY(mbar_addr, parity) do { \
    uint32_t _mb = (uint32_t)(mbar_addr); uint32_t _pa = (uint32_t)(parity); uint32_t _dn; \
    asm volatile("{\n\t.reg .pred p;\n\tmbarrier.try_wait.parity.acquire.cta.shared::cta.b64 p, [%1], %2;\n\tselp.b32 %0, 1, 0, p;\n\t}" \
        : "=r"(_dn) : "r"(_mb), "r"(_pa) : "memory"); \
    if (!_dn) { \
        asm volatile("{\n\t.reg .pred P1;\n\tWL_%=:\n\tmbarrier.try_wait.parity.acquire.cta.shared::cta.b64 P1, [%0], %1, 0x989680;\n\t@P1 bra.uni WD_%=;\n\tbra.uni WL_%=;\n\tWD_%=:\n\t}" \
            :: "r"(_mb), "r"(_pa) : "memory"); \
    } \
} while(0)

__device__ __forceinline__ void bulk_g2s(uint32_t dst, const void* src, uint32_t bytes, uint32_t mbar) {
    asm volatile("cp.async.bulk.shared::cta.global.mbarrier::complete_tx::bytes [%0], [%1], %2, [%3];"
        :: "r"(dst), "l"(src), "r"(bytes), "r"(mbar) : "memory");
}

#define LDSM_X4(r0, r1, r2, r3, addr) \
    asm volatile("ldmatrix.sync.aligned.m8n8.x4.shared.b16 {%0,%1,%2,%3}, [%4];" \
        : "=r"(r0), "=r"(r1), "=r"(r2), "=r"(r3) : "r"(addr))

#define MMA16816(d, a0, a1, a2, a3, b0, b1) \
    asm volatile("mma.sync.aligned.m16n8k16.row.col.f32.bf16.bf16.f32 " \
        "{%0,%1,%2,%3},{%4,%5,%6,%7},{%8,%9},{%0,%1,%2,%3};" \
        : "+f"((d)[0]), "+f"((d)[1]), "+f"((d)[2]), "+f"((d)[3]) \
        : "r"(a0), "r"(a1), "r"(a2), "r"(a3), "r"(b0), "r"(b1))

// hi/lo bf16 split helpers
__device__ __forceinline__ void split_pack(const float* a, uint32_t* hi, uint32_t* lo) {
    #pragma unroll
    for (int j = 0; j < 4; j++) {
        float f0 = a[2*j], f1 = a[2*j+1];
        __nv_bfloat16 h0 = __float2bfloat16(f0);
        __nv_bfloat16 h1 = __float2bfloat16(f1);
        float r0 = f0 - __bfloat162float(h0);
        float r1 = f1 - __bfloat162float(h1);
        __nv_bfloat16 l0 = __float2bfloat16(r0);
        __nv_bfloat16 l1 = __float2bfloat16(r1);
        hi[j] = (uint32_t)__bfloat16_as_ushort(h0) | ((uint32_t)__bfloat16_as_ushort(h1) << 16);
        lo[j] = (uint32_t)__bfloat16_as_ushort(l0) | ((uint32_t)__bfloat16_as_ushort(l1) << 16);
    }
}

// ============================================================
// Kernel 1: batch-invariant prep (kNN + relation MLP + zero stats)
// ============================================================
__global__ void prep_kernel(const float* __restrict__ verts,
                            const float* __restrict__ r_w1, const float* __restrict__ r_b1,
                            const float* __restrict__ r_w2, const float* __restrict__ r_b2)
{
    __shared__ float sv[VIEWS * 3];
    __shared__ float sd2[VIEWS * VIEWS];
    __shared__ int   sidx[VIEWS * KNN];
    int tid = threadIdx.x;

    if (tid < VIEWS * 3) sv[tid] = verts[tid];
    for (int i = tid; i < DIM; i += blockDim.x) { g_sum[i] = 0.f; g_sumsq[i] = 0.f; }
    __syncthreads();

    for (int t = tid; t < VIEWS * VIEWS; t += blockDim.x) {
        int n = t / VIEWS, m = t % VIEWS;
        float dx = sv[n*3+0] - sv[m*3+0];
        float dy = sv[n*3+1] - sv[m*3+1];
        float dz = sv[n*3+2] - sv[m*3+2];
        sd2[t] = dx*dx + dy*dy + dz*dz;
    }
    __syncthreads();

    if (tid < VIEWS) {
        unsigned used = 0u;
        for (int k = 0; k < KNN; k++) {
            float bd = 3.4e38f; int bi = 0;
            for (int m = 0; m < VIEWS; m++) {
                if (used & (1u << m)) continue;
                float dd = sd2[tid * VIEWS + m];
                if (dd < bd) { bd = dd; bi = m; }
            }
            used |= 1u << bi;
            sidx[tid * KNN + k] = bi;
            g_idx[tid * KNN + k] = bi;
        }
    }
    __syncthreads();

    if (tid < VIEWS * KNN) {
        int n = tid / KNN, k = tid % KNN;
        int i0 = sidx[n * KNN + 0];
        int ik = sidx[n * KNN + k];
        float v0x = sv[i0*3+0], v0y = sv[i0*3+1], v0z = sv[i0*3+2];
        float vkx = sv[ik*3+0], vky = sv[ik*3+1], vkz = sv[ik*3+2];
        float dvx = v0x - vkx, dvy = v0y - vky, dvz = v0z - vkz;
        float dn = sqrtf(dvx*dvx + dvy*dvy + dvz*dvz + 1e-12f);
        float vF[10] = {v0x, v0y, v0z, vkx, vky, vkz, dvx, dvy, dvz, dn};
        float e = r_b2[0];
        #pragma unroll
        for (int j = 0; j < 10; j++) {
            float a = r_b1[j];
            #pragma unroll
            for (int i = 0; i < 10; i++) a += vF[i] * r_w1[j*10 + i];
            e += fmaxf(a, 0.f) * r_w2[j];
        }
        g_e[tid] = e;
    }
}

// ============================================================
// Kernel 2: Conv2d(3->1, 3x3 valid). One block per image.
// Register-blocked: each thread computes 4 consecutive x outputs
// (54 LDS instead of 108 per 4 outputs).
// ============================================================
__global__ __launch_bounds__(256) void conv_kernel(const float* __restrict__ x,
                                                   const float* __restrict__ w,
                                                   const float* __restrict__ b)
{
    __shared__ float sx[IMG_ELEMS];
    __shared__ float sw[27];
    __shared__ float sb;
    int img = blockIdx.x;
    const float* xp = x + (size_t)img * IMG_ELEMS;
    for (int i = threadIdx.x; i < IMG_ELEMS; i += 256) sx[i] = xp[i];
    if (threadIdx.x < 27) sw[threadIdx.x] = w[threadIdx.x];
    if (threadIdx.x == 0) sb = b[0];
    __syncthreads();

    int oy  = threadIdx.x >> 3;          // 0..31
    int ox4 = (threadIdx.x & 7) * 4;     // 0,4,...,28

    float acc0 = sb, acc1 = sb, acc2 = sb, acc3 = sb;
    #pragma unroll
    for (int c = 0; c < 3; c++) {
        #pragma unroll
        for (int ky = 0; ky < 3; ky++) {
            const float* rp = &sx[c*1156 + (oy+ky)*34 + ox4];
            float v0 = rp[0], v1 = rp[1], v2 = rp[2], v3 = rp[3], v4 = rp[4], v5 = rp[5];
            float w0 = sw[c*9 + ky*3 + 0], w1 = sw[c*9 + ky*3 + 1], w2 = sw[c*9 + ky*3 + 2];
            acc0 += v0*w0 + v1*w1 + v2*w2;
            acc1 += v1*w0 + v2*w1 + v3*w2;
            acc2 += v2*w0 + v3*w1 + v4*w2;
            acc3 += v3*w0 + v4*w1 + v5*w2;
        }
    }
    float4* out = (float4*)(g_F + (size_t)img * DIM + oy * 32 + ox4);
    *out = make_float4(acc0, acc1, acc2, acc3);
}

// ============================================================
// Kernel 3: gather + bf16 hi/lo split, written pre-swizzled
// into chunk-blocked layout: [chunk][row][128B], 16B unit uu
// stored at position (uu ^ (row&7)).
// ============================================================
__global__ __launch_bounds__(256) void gather_kernel(int rows)
{
    int t = threadIdx.x;
    int r = blockIdx.x * 2 + (t >> 7);
    int u = t & 127;
    int c = u >> 3, uu = u & 7;
    int n = r & (VIEWS - 1), b = r >> 5;

    float e[KNN]; int id[KNN];
    #pragma unroll
    for (int k = 0; k < KNN; k++) { e[k] = g_e[n*KNN+k]; id[k] = g_idx[n*KNN+k]; }

    float acc[8];
    #pragma unroll
    for (int j = 0; j < 8; j++) acc[j] = 0.f;

    const float* base = g_F + ((size_t)b << 5) * DIM + c * 64 + uu * 8;
    #pragma unroll
    for (int k = 0; k < KNN; k++) {
        const float4* p = (const float4*)(base + (size_t)id[k] * DIM);
        float4 v0 = p[0], v1 = p[1];
        float ek = e[k];
        acc[0] += ek*v0.x; acc[1] += ek*v0.y; acc[2] += ek*v0.z; acc[3] += ek*v0.w;
        acc[4] += ek*v1.x; acc[5] += ek*v1.y; acc[6] += ek*v1.z; acc[7] += ek*v1.w;
    }

    uint32_t hi[4], lo[4];
    split_pack(acc, hi, lo);

    size_t off = ((size_t)c * rows + r) * 128 + (size_t)((uu ^ (r & 7)) << 4);
    *(uint4*)(g_Ahi + off) = make_uint4(hi[0], hi[1], hi[2], hi[3]);
    *(uint4*)(g_Alo + off) = make_uint4(lo[0], lo[1], lo[2], lo[3]);
}

// ============================================================
// Kernel 4: convert W (1024x1024 fp32, [n][k]) to bf16 hi/lo,
// pre-swizzled chunk-blocked.
// ============================================================
__global__ __launch_bounds__(256) void convw_kernel(const float* __restrict__ W)
{
    int t = threadIdx.x;
    int r = blockIdx.x * 2 + (t >> 7);
    int u = t & 127;
    int c = u >> 3, uu = u & 7;

    const float4* p = (const float4*)(W + (size_t)r * DIM + c * 64 + uu * 8);
    float4 v0 = p[0], v1 = p[1];
    float a[8] = {v0.x, v0.y, v0.z, v0.w, v1.x, v1.y, v1.z, v1.w};

    uint32_t hi[4], lo[4];
    split_pack(a, hi, lo);

    size_t off = ((size_t)c * DIM + r) * 128 + (size_t)((uu ^ (r & 7)) << 4);
    *(uint4*)(g_Bhi + off) = make_uint4(hi[0], hi[1], hi[2], hi[3]);
    *(uint4*)(g_Blo + off) = make_uint4(lo[0], lo[1], lo[2], lo[3]);
}

// ============================================================
// Kernel 5: mma.sync bf16 GEMM  z = Fa @ W^T + bias.
// CTA tile 128x128, K-chunk 64, 3-stage cp.async.bulk pipeline.
// 8 warps as 2(M) x 4(N); warp tile 64x32; m16n8k16 bf16 MMA.
// 3-pass split, pass-major ordering (dep distance 16 MMAs):
// AhiBhi, then AhiBlo, then AloBhi.
// ============================================================
#define STAGE_BYTES 65536   // Ahi 16K | Alo 16K | Bhi 16K | Blo 16K
#define GEMM_SMEM (NSTAGE * STAGE_BYTES)

__global__ void __launch_bounds__(256, 1) gemm_kernel(const float* __restrict__ lin_b,
                                                      float* __restrict__ z, int rows)
{
    extern __shared__ __align__(1024) unsigned char smem[];
    __shared__ uint64_t mbar_store[NSTAGE];
    uint32_t sbase = smem_u32(smem);
    uint32_t mb = smem_u32(mbar_store);

    int tid = threadIdx.x;
    int wid = tid >> 5, lane = tid & 31;
    int wm = wid >> 2;        // 0..1  (M half, 64 rows)
    int wn = wid & 3;         // 0..3  (N quarter, 32 cols)

    int m0 = blockIdx.y * 128;
    int n0 = blockIdx.x * 128;

    if (tid == 0) {
        #pragma unroll
        for (int s = 0; s < NSTAGE; s++) MBARRIER_INIT(mb + s * 8, 1);
        asm volatile("fence.proxy.async.shared::cta;" ::: "memory");
    }
    __syncthreads();

    // prologue: stage chunks 0..NSTAGE-1
    if (tid == 0) {
        #pragma unroll
        for (int c = 0; c < NSTAGE; c++) {
            uint32_t fullb = mb + c * 8;
            MBARRIER_EXPECT_TX(fullb, (uint32_t)STAGE_BYTES);
            uint32_t base = sbase + c * STAGE_BYTES;
            size_t aoff = ((size_t)c * rows + m0) * 128;
            size_t boff = ((size_t)c * DIM + n0) * 128;
            bulk_g2s(base,          g_Ahi + aoff, 16384, fullb);
            bulk_g2s(base + 16384,  g_Alo + aoff, 16384, fullb);
            bulk_g2s(base + 32768,  g_Bhi + boff, 16384, fullb);
            bulk_g2s(base + 49152,  g_Blo + boff, 16384, fullb);
        }
    }

    // per-thread ldmatrix addressing
    int lrow8 = (lane & 7) + ((lane >> 3) & 1) * 8;  // 0..15 row within 16-row tile
    int ksel  = lane >> 4;                            // 0/1: k-seg select within k16

    uint32_t a_rowoff[4]; int a_sw[4];
    #pragma unroll
    for (int mt = 0; mt < 4; mt++) {
        int rw = wm * 64 + mt * 16 + lrow8;
        a_rowoff[mt] = (uint32_t)rw * 128;
        a_sw[mt] = rw & 7;
    }
    uint32_t b_rowoff[2]; int b_sw[2];
    #pragma unroll
    for (int np = 0; np < 2; np++) {
        int rw = wn * 32 + np * 16 + lrow8;
        b_rowoff[np] = (uint32_t)rw * 128;
        b_sw[np] = rw & 7;
    }

    float acc[4][4][4];
    #pragma unroll
    for (int mt = 0; mt < 4; mt++)
        #pragma unroll
        for (int nt = 0; nt < 4; nt++)
            #pragma unroll
            for (int j = 0; j < 4; j++) acc[mt][nt][j] = 0.f;

    int s = 0, ph = 0;
    for (int c = 0; c < NCHUNK; c++) {
        MBARRIER_WAIT_PARITY(mb + s * 8, ph);

        uint32_t stA  = sbase + s * STAGE_BYTES;
        uint32_t stAl = stA + 16384;
        uint32_t stB  = stA + 32768;
        uint32_t stBl = stA + 49152;

        #pragma unroll
        for (int kk = 0; kk < 4; kk++) {
            int kseg = (kk << 1) | ksel;
            uint32_t ah[4][4], al[4][4], bh[2][4], bl[2][4];
            #pragma unroll
            for (int mt = 0; mt < 4; mt++) {
                uint32_t offa = a_rowoff[mt] + (uint32_t)((kseg ^ a_sw[mt]) << 4);
                LDSM_X4(ah[mt][0], ah[mt][1], ah[mt][2], ah[mt][3], stA  + offa);
                LDSM_X4(al[mt][0], al[mt][1], al[mt][2], al[mt][3], stAl + offa);
            }
            #pragma unroll
            for (int np = 0; np < 2; np++) {
                uint32_t offb = b_rowoff[np] + (uint32_t)((kseg ^ b_sw[np]) << 4);
                LDSM_X4(bh[np][0], bh[np][1], bh[np][2], bh[np][3], stB  + offb);
                LDSM_X4(bl[np][0], bl[np][1], bl[np][2], bl[np][3], stBl + offb);
            }
            // pass 1: Ahi * Bhi  (16 independent accumulators)
            #pragma unroll
            for (int mt = 0; mt < 4; mt++)
                #pragma unroll
                for (int nt = 0; nt < 4; nt++) {
                    int np = nt >> 1, sel = nt & 1;
                    MMA16816(acc[mt][nt], ah[mt][0], ah[mt][1], ah[mt][2], ah[mt][3],
                             bh[np][sel], bh[np][sel + 2]);
                }
            // pass 2: Ahi * Blo
            #pragma unroll
            for (int mt = 0; mt < 4; mt++)
                #pragma unroll
                for (int nt = 0; nt < 4; nt++) {
                    int np = nt >> 1, sel = nt & 1;
                    MMA16816(acc[mt][nt], ah[mt][0], ah[mt][1], ah[mt][2], ah[mt][3],
                             bl[np][sel], bl[np][sel + 2]);
                }
            // pass 3: Alo * Bhi
            #pragma unroll
            for (int mt = 0; mt < 4; mt++)
                #pragma unroll
                for (int nt = 0; nt < 4; nt++) {
                    int np = nt >> 1, sel = nt & 1;
                    MMA16816(acc[mt][nt], al[mt][0], al[mt][1], al[mt][2], al[mt][3],
                             bh[np][sel], bh[np][sel + 2]);
                }
        }

        __syncthreads();   // all warps done reading stage s
        if (tid == 0 && c + NSTAGE < NCHUNK) {
            int cn = c + NSTAGE;
            uint32_t fullb = mb + s * 8;
            MBARRIER_EXPECT_TX(fullb, (uint32_t)STAGE_BYTES);
            uint32_t base = sbase + s * STAGE_BYTES;
            size_t aoff = ((size_t)cn * rows + m0) * 128;
            size_t boff = ((size_t)cn * DIM + n0) * 128;
            bulk_g2s(base,          g_Ahi + aoff, 16384, fullb);
            bulk_g2s(base + 16384,  g_Alo + aoff, 16384, fullb);
            bulk_g2s(base + 32768,  g_Bhi + boff, 16384, fullb);
            bulk_g2s(base + 49152,  g_Blo + boff, 16384, fullb);
        }
        if (++s == NSTAGE) { s = 0; ph ^= 1; }
    }

    // epilogue: acc -> z + bias
    int qr = lane >> 2;          // 0..7
    int qc = (lane & 3) * 2;     // 0,2,4,6
    #pragma unroll
    for (int nt = 0; nt < 4; nt++) {
        int cb = n0 + wn * 32 + nt * 8 + qc;
        float b0 = __ldg(lin_b + cb);
        float b1 = __ldg(lin_b + cb + 1);
        #pragma unroll
        for (int mt = 0; mt < 4; mt++) {
            int mr = m0 + wm * 64 + mt * 16 + qr;
            float2* p0 = (float2*)(z + (size_t)mr * DIM + cb);
            float2* p1 = (float2*)(z + (size_t)(mr + 8) * DIM + cb);
            *p0 = make_float2(acc[mt][nt][0] + b0, acc[mt][nt][1] + b1);
            *p1 = make_float2(acc[mt][nt][2] + b0, acc[mt][nt][3] + b1);
        }
    }
}

// ============================================================
// Kernel 6: per-column sum / sumsq over z (float4 loads)
// ============================================================
__global__ __launch_bounds__(256) void stats_kernel(const float* __restrict__ z)
{
    int t = threadIdx.x;
    int r0 = blockIdx.x * 64;
    float s[4] = {0.f, 0.f, 0.f, 0.f};
    float q[4] = {0.f, 0.f, 0.f, 0.f};
    const float4* zp = (const float4*)(z + (size_t)r0 * DIM) + t;
    for (int r = 0; r < 64; r++) {
        float4 v = zp[(size_t)r * (DIM / 4)];
        s[0] += v.x; q[0] += v.x * v.x;
        s[1] += v.y; q[1] += v.y * v.y;
        s[2] += v.z; q[2] += v.z * v.z;
        s[3] += v.w; q[3] += v.w * v.w;
    }
    int c = t * 4;
    #pragma unroll
    for (int j = 0; j < 4; j++) {
        atomicAdd(&g_sum[c + j], s[j]);
        atomicAdd(&g_sumsq[c + j], q[j]);
    }
}

// ============================================================
// Kernel 7: finalize BN coefficients
// ============================================================
__global__ void finalize_kernel(const float* __restrict__ bn_g,
                                const float* __restrict__ bn_b, float invN)
{
    int d = blockIdx.x * blockDim.x + threadIdx.x;
    if (d < DIM) {
        float mean = g_sum[d] * invN;
        float var  = g_sumsq[d] * invN - mean * mean;
        float istd = rsqrtf(var + 1e-5f);
        float a = istd * bn_g[d];
        g_scale[d] = a;
        g_shift[d] = bn_b[d] - mean * a;
    }
}

// ============================================================
// Kernel 8: BN apply + leaky relu in place
// ============================================================
__global__ __launch_bounds__(256) void bn_kernel(float* __restrict__ z, int n4)
{
    int stride = gridDim.x * blockDim.x;
    for (int i = blockIdx.x * blockDim.x + threadIdx.x; i < n4; i += stride) {
        float4 v = ((const float4*)z)[i];
        int c = (i * 4) & (DIM - 1);
        float y0 = v.x * g_scale[c+0] + g_shift[c+0];
        float y1 = v.y * g_scale[c+1] + g_shift[c+1];
        float y2 = v.z * g_scale[c+2] + g_shift[c+2];
        float y3 = v.w * g_scale[c+3] + g_shift[c+3];
        y0 = (y0 >= 0.f) ? y0 : 0.2f * y0;
        y1 = (y1 >= 0.f) ? y1 : 0.2f * y1;
        y2 = (y2 >= 0.f) ? y2 : 0.2f * y2;
        y3 = (y3 >= 0.f) ? y3 : 0.2f * y3;
        ((float4*)z)[i] = make_float4(y0, y1, y2, y3);
    }
}

// ============================================================
// Launch
// ============================================================
extern "C" void kernel_launch(void* const* d_in, const int* in_sizes, int n_in,
                              void* d_out, int out_size)
{
    const float* x      = (const float*)d_in[0];
    const float* verts  = (const float*)d_in[1];
    const float* conv_w = (const float*)d_in[2];
    const float* conv_b = (const float*)d_in[3];
    const float* r_w1   = (const float*)d_in[4];
    const float* r_b1   = (const float*)d_in[5];
    const float* r_w2   = (const float*)d_in[6];
    const float* r_b2   = (const float*)d_in[7];
    const float* lin_w  = (const float*)d_in[8];
    const float* lin_b  = (const float*)d_in[9];
    const float* bn_g   = (const float*)d_in[10];
    const float* bn_b   = (const float*)d_in[11];
    float* out = (float*)d_out;

    int rows = in_sizes[0] / IMG_ELEMS;   // B*VIEWS = 16384

    cudaFuncSetAttribute(gemm_kernel, cudaFuncAttributeMaxDynamicSharedMemorySize, GEMM_SMEM);

    prep_kernel<<<1, 256>>>(verts, r_w1, r_b1, r_w2, r_b2);
    conv_kernel<<<rows, 256>>>(x, conv_w, conv_b);
    convw_kernel<<<DIM / 2, 256>>>(lin_w);
    gather_kernel<<<rows / 2, 256>>>(rows);
    gemm_kernel<<<dim3(DIM / 128, rows / 128), 256, GEMM_SMEM>>>(lin_b, out, rows);
    stats_kernel<<<rows / 64, 256>>>(out);
    finalize_kernel<<<(DIM + 255) / 256, 256>>>(bn_g, bn_b, 1.0f / (float)rows);
    bn_kernel<<<2048, 256>>>(out, rows * DIM / 4);
}

// round 15
// speedup vs baseline: 1.2831x; 1.2831x over previous
#include <cuda_runtime.h>
#include <cuda_bf16.h>
#include <math.h>
#include <stdint.h>

#define VIEWS 32
#define KNN 5
#define DIM 1024
#define MAXROWS 16384
#define IMG_ELEMS (3*34*34)   // 3468
#define NCHUNK 16             // K chunks of 64 bf16 (128B)

// ---------------- static device scratch (no allocation allowed) ----------------
__device__ float g_F [(size_t)MAXROWS * DIM];                       // conv features (fp32)
__device__ __align__(1024) unsigned char g_Ahi[(size_t)NCHUNK * MAXROWS * 128];  // 32MB
__device__ __align__(1024) unsigned char g_Alo[(size_t)NCHUNK * MAXROWS * 128];  // 32MB
__device__ __align__(1024) unsigned char g_Bhi[(size_t)NCHUNK * DIM * 128];      // 2MB
__device__ __align__(1024) unsigned char g_Blo[(size_t)NCHUNK * DIM * 128];      // 2MB
__device__ int   g_idx[VIEWS * KNN];
__device__ float g_e  [VIEWS * KNN];
__device__ float g_sum  [DIM];
__device__ float g_sumsq[DIM];
__device__ float g_scale[DIM];
__device__ float g_shift[DIM];

// ---------------- PTX helpers (all portable to plain sm_103 target) ----------------
__device__ __forceinline__ uint32_t smem_u32(const void* p) {
    uint32_t a;
    asm("{ .reg .u64 t; cvta.to.shared.u64 t, %1; cvt.u32.u64 %0, t; }" : "=r"(a) : "l"(p));
    return a;
}

#define MBARRIER_INIT(addr, cnt) \
    asm volatile("mbarrier.init.shared.b64 [%0], %1;" :: "r"((uint32_t)(addr)), "r"((uint32_t)(cnt)) : "memory")

#define MBARRIER_EXPECT_TX(addr, bytes) \
    asm volatile("mbarrier.arrive.expect_tx.shared.b64 _, [%0], %1;" :: "r"((uint32_t)(addr)), "r"((uint32_t)(bytes)) : "memory")

#define MBARRIER_WAIT_PARITY(mbar_addr, parity) do { \
    uint32_t _mb = (uint32_t)(mbar_addr); uint32_t _pa = (uint32_t)(parity); uint32_t _dn; \
    asm volatile("{\n\t.reg .pred p;\n\tmbarrier.try_wait.parity.acquire.cta.shared::cta.b64 p, [%1], %2;\n\tselp.b32 %0, 1, 0, p;\n\t}" \
        : "=r"(_dn) : "r"(_mb), "r"(_pa) : "memory"); \
    if (!_dn) { \
        asm volatile("{\n\t.reg .pred P1;\n\tWL_%=:\n\tmbarrier.try_wait.parity.acquire.cta.shared::cta.b64 P1, [%0], %1, 0x989680;\n\t@P1 bra.uni WD_%=;\n\tbra.uni WL_%=;\n\tWD_%=:\n\t}" \
            :: "r"(_mb), "r"(_pa) : "memory"); \
    } \
} while(0)

__device__ __forceinline__ void bulk_g2s(uint32_t dst, const void* src, uint32_t bytes, uint32_t mbar) {
    asm volatile("cp.async.bulk.shared::cta.global.mbarrier::complete_tx::bytes [%0], [%1], %2, [%3];"
        :: "r"(dst), "l"(src), "r"(bytes), "r"(mbar) : "memory");
}

#define LDSM_X4(r0, r1, r2, r3, addr) \
    asm volatile("ldmatrix.sync.aligned.m8n8.x4.shared.b16 {%0,%1,%2,%3}, [%4];" \
        : "=r"(r0), "=r"(r1), "=r"(r2), "=r"(r3) : "r"(addr))

#define MMA16816(d, a0, a1, a2, a3, b0, b1) \
    asm volatile("mma.sync.aligned.m16n8k16.row.col.f32.bf16.bf16.f32 " \
        "{%0,%1,%2,%3},{%4,%5,%6,%7},{%8,%9},{%0,%1,%2,%3};" \
        : "+f"((d)[0]), "+f"((d)[1]), "+f"((d)[2]), "+f"((d)[3]) \
        : "r"(a0), "r"(a1), "r"(a2), "r"(a3), "r"(b0), "r"(b1))

// hi/lo bf16 split helpers
__device__ __forceinline__ void split_pack(const float* a, uint32_t* hi, uint32_t* lo) {
    #pragma unroll
    for (int j = 0; j < 4; j++) {
        float f0 = a[2*j], f1 = a[2*j+1];
        __nv_bfloat16 h0 = __float2bfloat16(f0);
        __nv_bfloat16 h1 = __float2bfloat16(f1);
        float r0 = f0 - __bfloat162float(h0);
        float r1 = f1 - __bfloat162float(h1);
        __nv_bfloat16 l0 = __float2bfloat16(r0);
        __nv_bfloat16 l1 = __float2bfloat16(r1);
        hi[j] = (uint32_t)__bfloat16_as_ushort(h0) | ((uint32_t)__bfloat16_as_ushort(h1) << 16);
        lo[j] = (uint32_t)__bfloat16_as_ushort(l0) | ((uint32_t)__bfloat16_as_ushort(l1) << 16);
    }
}

// ============================================================
// Kernel 1: batch-invariant prep (kNN + relation MLP + zero stats)
// ============================================================
__global__ void prep_kernel(const float* __restrict__ verts,
                            const float* __restrict__ r_w1, const float* __restrict__ r_b1,
                            const float* __restrict__ r_w2, const float* __restrict__ r_b2)
{
    __shared__ float sv[VIEWS * 3];
    __shared__ float sd2[VIEWS * VIEWS];
    __shared__ int   sidx[VIEWS * KNN];
    int tid = threadIdx.x;

    if (tid < VIEWS * 3) sv[tid] = verts[tid];
    for (int i = tid; i < DIM; i += blockDim.x) { g_sum[i] = 0.f; g_sumsq[i] = 0.f; }
    __syncthreads();

    for (int t = tid; t < VIEWS * VIEWS; t += blockDim.x) {
        int n = t / VIEWS, m = t % VIEWS;
        float dx = sv[n*3+0] - sv[m*3+0];
        float dy = sv[n*3+1] - sv[m*3+1];
        float dz = sv[n*3+2] - sv[m*3+2];
        sd2[t] = dx*dx + dy*dy + dz*dz;
    }
    __syncthreads();

    if (tid < VIEWS) {
        unsigned used = 0u;
        for (int k = 0; k < KNN; k++) {
            float bd = 3.4e38f; int bi = 0;
            for (int m = 0; m < VIEWS; m++) {
                if (used & (1u << m)) continue;
                float dd = sd2[tid * VIEWS + m];
                if (dd < bd) { bd = dd; bi = m; }
            }
            used |= 1u << bi;
            sidx[tid * KNN + k] = bi;
            g_idx[tid * KNN + k] = bi;
        }
    }
    __syncthreads();

    if (tid < VIEWS * KNN) {
        int n = tid / KNN, k = tid % KNN;
        int i0 = sidx[n * KNN + 0];
        int ik = sidx[n * KNN + k];
        float v0x = sv[i0*3+0], v0y = sv[i0*3+1], v0z = sv[i0*3+2];
        float vkx = sv[ik*3+0], vky = sv[ik*3+1], vkz = sv[ik*3+2];
        float dvx = v0x - vkx, dvy = v0y - vky, dvz = v0z - vkz;
        float dn = sqrtf(dvx*dvx + dvy*dvy + dvz*dvz + 1e-12f);
        float vF[10] = {v0x, v0y, v0z, vkx, vky, vkz, dvx, dvy, dvz, dn};
        float e = r_b2[0];
        #pragma unroll
        for (int j = 0; j < 10; j++) {
            float a = r_b1[j];
            #pragma unroll
            for (int i = 0; i < 10; i++) a += vF[i] * r_w1[j*10 + i];
            e += fmaxf(a, 0.f) * r_w2[j];
        }
        g_e[tid] = e;
    }
}

// ============================================================
// Kernel 2: Conv2d(3->1, 3x3 valid). One block per image.
// ============================================================
__global__ __launch_bounds__(256) void conv_kernel(const float* __restrict__ x,
                                                   const float* __restrict__ w,
                                                   const float* __restrict__ b)
{
    __shared__ float sx[IMG_ELEMS];
    __shared__ float sw[27];
    __shared__ float sb;
    int img = blockIdx.x;
    const float* xp = x + (size_t)img * IMG_ELEMS;
    for (int i = threadIdx.x; i < IMG_ELEMS; i += 256) sx[i] = xp[i];
    if (threadIdx.x < 27) sw[threadIdx.x] = w[threadIdx.x];
    if (threadIdx.x == 0) sb = b[0];
    __syncthreads();

    float* out = g_F + (size_t)img * DIM;
    for (int p = threadIdx.x; p < DIM; p += 256) {
        int oy = p >> 5, ox = p & 31;
        float acc = sb;
        #pragma unroll
        for (int c = 0; c < 3; c++)
            #pragma unroll
            for (int ky = 0; ky < 3; ky++)
                #pragma unroll
                for (int kx = 0; kx < 3; kx++)
                    acc += sx[c*1156 + (oy+ky)*34 + (ox+kx)] * sw[c*9 + ky*3 + kx];
        out[p] = acc;
    }
}

// ============================================================
// Kernel 3: gather + bf16 hi/lo split, written pre-swizzled
// into chunk-blocked layout: [chunk][row][128B], 16B unit uu
// stored at position (uu ^ (row&7)).
// ============================================================
__global__ __launch_bounds__(256) void gather_kernel(int rows)
{
    int t = threadIdx.x;
    int r = blockIdx.x * 2 + (t >> 7);
    int u = t & 127;
    int c = u >> 3, uu = u & 7;
    int n = r & (VIEWS - 1), b = r >> 5;

    float e[KNN]; int id[KNN];
    #pragma unroll
    for (int k = 0; k < KNN; k++) { e[k] = g_e[n*KNN+k]; id[k] = g_idx[n*KNN+k]; }

    float acc[8];
    #pragma unroll
    for (int j = 0; j < 8; j++) acc[j] = 0.f;

    const float* base = g_F + ((size_t)b << 5) * DIM + c * 64 + uu * 8;
    #pragma unroll
    for (int k = 0; k < KNN; k++) {
        const float4* p = (const float4*)(base + (size_t)id[k] * DIM);
        float4 v0 = p[0], v1 = p[1];
        float ek = e[k];
        acc[0] += ek*v0.x; acc[1] += ek*v0.y; acc[2] += ek*v0.z; acc[3] += ek*v0.w;
        acc[4] += ek*v1.x; acc[5] += ek*v1.y; acc[6] += ek*v1.z; acc[7] += ek*v1.w;
    }

    uint32_t hi[4], lo[4];
    split_pack(acc, hi, lo);

    size_t off = ((size_t)c * rows + r) * 128 + (size_t)((uu ^ (r & 7)) << 4);
    *(uint4*)(g_Ahi + off) = make_uint4(hi[0], hi[1], hi[2], hi[3]);
    *(uint4*)(g_Alo + off) = make_uint4(lo[0], lo[1], lo[2], lo[3]);
}

// ============================================================
// Kernel 4: convert W (1024x1024 fp32, [n][k]) to bf16 hi/lo,
// pre-swizzled chunk-blocked.
// ============================================================
__global__ __launch_bounds__(256) void convw_kernel(const float* __restrict__ W)
{
    int t = threadIdx.x;
    int r = blockIdx.x * 2 + (t >> 7);
    int u = t & 127;
    int c = u >> 3, uu = u & 7;

    const float4* p = (const float4*)(W + (size_t)r * DIM + c * 64 + uu * 8);
    float4 v0 = p[0], v1 = p[1];
    float a[8] = {v0.x, v0.y, v0.z, v0.w, v1.x, v1.y, v1.z, v1.w};

    uint32_t hi[4], lo[4];
    split_pack(a, hi, lo);

    size_t off = ((size_t)c * DIM + r) * 128 + (size_t)((uu ^ (r & 7)) << 4);
    *(uint4*)(g_Bhi + off) = make_uint4(hi[0], hi[1], hi[2], hi[3]);
    *(uint4*)(g_Blo + off) = make_uint4(lo[0], lo[1], lo[2], lo[3]);
}

// ============================================================
// Kernel 5: mma.sync bf16 GEMM  z = Fa @ W^T + bias.
// CTA tile 128x128, K-chunk 64, double-buffered cp.async.bulk.
// 8 warps as 2(M) x 4(N); warp tile 64x32; m16n8k16 bf16 MMA.
// 3-pass split folded: AhiBhi + AhiBlo + AloBhi.
// ============================================================
#define STAGE_BYTES 65536   // Ahi 16K | Alo 16K | Bhi 16K | Blo 16K
#define GEMM_SMEM (2 * STAGE_BYTES)

__global__ void __launch_bounds__(256, 1) gemm_kernel(const float* __restrict__ lin_b,
                                                      float* __restrict__ z, int rows)
{
    extern __shared__ __align__(1024) unsigned char smem[];
    __shared__ uint64_t mbar_store[2];
    uint32_t sbase = smem_u32(smem);
    uint32_t mb = smem_u32(mbar_store);

    int tid = threadIdx.x;
    int wid = tid >> 5, lane = tid & 31;
    int wm = wid >> 2;        // 0..1  (M half, 64 rows)
    int wn = wid & 3;         // 0..3  (N quarter, 32 cols)

    int m0 = blockIdx.y * 128;
    int n0 = blockIdx.x * 128;

    if (tid == 0) {
        MBARRIER_INIT(mb + 0, 1);
        MBARRIER_INIT(mb + 8, 1);
        asm volatile("fence.proxy.async.shared::cta;" ::: "memory");
    }
    __syncthreads();

    // prologue: stage chunks 0 and 1
    if (tid == 0) {
        #pragma unroll
        for (int c = 0; c < 2; c++) {
            uint32_t fullb = mb + c * 8;
            MBARRIER_EXPECT_TX(fullb, (uint32_t)STAGE_BYTES);
            uint32_t base = sbase + c * STAGE_BYTES;
            size_t aoff = ((size_t)c * rows + m0) * 128;
            size_t boff = ((size_t)c * DIM + n0) * 128;
            bulk_g2s(base,          g_Ahi + aoff, 16384, fullb);
            bulk_g2s(base + 16384,  g_Alo + aoff, 16384, fullb);
            bulk_g2s(base + 32768,  g_Bhi + boff, 16384, fullb);
            bulk_g2s(base + 49152,  g_Blo + boff, 16384, fullb);
        }
    }

    // per-thread ldmatrix addressing
    int lrow8 = (lane & 7) + ((lane >> 3) & 1) * 8;  // 0..15 row within 16-row tile
    int ksel  = lane >> 4;                            // 0/1: k-seg select within k16

    // A rows for this thread, 4 m-tiles
    uint32_t a_rowoff[4]; int a_sw[4];
    #pragma unroll
    for (int mt = 0; mt < 4; mt++) {
        int rw = wm * 64 + mt * 16 + lrow8;
        a_rowoff[mt] = (uint32_t)rw * 128;
        a_sw[mt] = rw & 7;
    }
    // B rows, 2 n-pairs (each covers 16 n)
    uint32_t b_rowoff[2]; int b_sw[2];
    #pragma unroll
    for (int np = 0; np < 2; np++) {
        int rw = wn * 32 + np * 16 + lrow8;
        b_rowoff[np] = (uint32_t)rw * 128;
        b_sw[np] = rw & 7;
    }

    float acc[4][4][4];
    #pragma unroll
    for (int mt = 0; mt < 4; mt++)
        #pragma unroll
        for (int nt = 0; nt < 4; nt++)
            #pragma unroll
            for (int j = 0; j < 4; j++) acc[mt][nt][j] = 0.f;

    for (int c = 0; c < NCHUNK; c++) {
        int s = c & 1;
        int ph = (c >> 1) & 1;
        MBARRIER_WAIT_PARITY(mb + s * 8, ph);

        uint32_t stA = sbase + s * STAGE_BYTES;
        uint32_t stAl = stA + 16384;
        uint32_t stB  = stA + 32768;
        uint32_t stBl = stA + 49152;

        #pragma unroll
        for (int kk = 0; kk < 4; kk++) {
            int kseg = (kk << 1) | ksel;
            uint32_t ah[4][4], al[4][4], bh[2][4], bl[2][4];
            #pragma unroll
            for (int mt = 0; mt < 4; mt++) {
                uint32_t offa = a_rowoff[mt] + (uint32_t)((kseg ^ a_sw[mt]) << 4);
                LDSM_X4(ah[mt][0], ah[mt][1], ah[mt][2], ah[mt][3], stA  + offa);
                LDSM_X4(al[mt][0], al[mt][1], al[mt][2], al[mt][3], stAl + offa);
            }
            #pragma unroll
            for (int np = 0; np < 2; np++) {
                uint32_t offb = b_rowoff[np] + (uint32_t)((kseg ^ b_sw[np]) << 4);
                LDSM_X4(bh[np][0], bh[np][1], bh[np][2], bh[np][3], stB  + offb);
                LDSM_X4(bl[np][0], bl[np][1], bl[np][2], bl[np][3], stBl + offb);
            }
            #pragma unroll
            for (int mt = 0; mt < 4; mt++) {
                #pragma unroll
                for (int nt = 0; nt < 4; nt++) {
                    int np = nt >> 1, sel = nt & 1;
                    uint32_t bh0 = bh[np][sel], bh1 = bh[np][sel + 2];
                    uint32_t bl0 = bl[np][sel], bl1 = bl[np][sel + 2];
                    MMA16816(acc[mt][nt], ah[mt][0], ah[mt][1], ah[mt][2], ah[mt][3], bh0, bh1);
                    MMA16816(acc[mt][nt], ah[mt][0], ah[mt][1], ah[mt][2], ah[mt][3], bl0, bl1);
                    MMA16816(acc[mt][nt], al[mt][0], al[mt][1], al[mt][2], al[mt][3], bh0, bh1);
                }
            }
        }

        __syncthreads();   // all warps done reading stage s
        if (tid == 0 && c + 2 < NCHUNK) {
            int cn = c + 2;
            uint32_t fullb = mb + s * 8;
            MBARRIER_EXPECT_TX(fullb, (uint32_t)STAGE_BYTES);
            uint32_t base = sbase + s * STAGE_BYTES;
            size_t aoff = ((size_t)cn * rows + m0) * 128;
            size_t boff = ((size_t)cn * DIM + n0) * 128;
            bulk_g2s(base,          g_Ahi + aoff, 16384, fullb);
            bulk_g2s(base + 16384,  g_Alo + aoff, 16384, fullb);
            bulk_g2s(base + 32768,  g_Bhi + boff, 16384, fullb);
            bulk_g2s(base + 49152,  g_Blo + boff, 16384, fullb);
        }
    }

    // epilogue: acc -> z + bias
    int qr = lane >> 2;          // 0..7
    int qc = (lane & 3) * 2;     // 0,2,4,6
    #pragma unroll
    for (int nt = 0; nt < 4; nt++) {
        int cb = n0 + wn * 32 + nt * 8 + qc;
        float b0 = __ldg(lin_b + cb);
        float b1 = __ldg(lin_b + cb + 1);
        #pragma unroll
        for (int mt = 0; mt < 4; mt++) {
            int mr = m0 + wm * 64 + mt * 16 + qr;
            float2* p0 = (float2*)(z + (size_t)mr * DIM + cb);
            float2* p1 = (float2*)(z + (size_t)(mr + 8) * DIM + cb);
            *p0 = make_float2(acc[mt][nt][0] + b0, acc[mt][nt][1] + b1);
            *p1 = make_float2(acc[mt][nt][2] + b0, acc[mt][nt][3] + b1);
        }
    }
}

// ============================================================
// Kernel 6: per-column sum / sumsq over z (float4 loads)
// ============================================================
__global__ __launch_bounds__(256) void stats_kernel(const float* __restrict__ z)
{
    int t = threadIdx.x;
    int r0 = blockIdx.x * 64;
    float s[4] = {0.f, 0.f, 0.f, 0.f};
    float q[4] = {0.f, 0.f, 0.f, 0.f};
    const float4* zp = (const float4*)(z + (size_t)r0 * DIM) + t;
    for (int r = 0; r < 64; r++) {
        float4 v = zp[(size_t)r * (DIM / 4)];
        s[0] += v.x; q[0] += v.x * v.x;
        s[1] += v.y; q[1] += v.y * v.y;
        s[2] += v.z; q[2] += v.z * v.z;
        s[3] += v.w; q[3] += v.w * v.w;
    }
    int c = t * 4;
    #pragma unroll
    for (int j = 0; j < 4; j++) {
        atomicAdd(&g_sum[c + j], s[j]);
        atomicAdd(&g_sumsq[c + j], q[j]);
    }
}

// ============================================================
// Kernel 7: finalize BN coefficients
// ============================================================
__global__ void finalize_kernel(const float* __restrict__ bn_g,
                                const float* __restrict__ bn_b, float invN)
{
    int d = blockIdx.x * blockDim.x + threadIdx.x;
    if (d < DIM) {
        float mean = g_sum[d] * invN;
        float var  = g_sumsq[d] * invN - mean * mean;
        float istd = rsqrtf(var + 1e-5f);
        float a = istd * bn_g[d];
        g_scale[d] = a;
        g_shift[d] = bn_b[d] - mean * a;
    }
}

// ============================================================
// Kernel 8: BN apply + leaky relu in place
// ============================================================
__global__ __launch_bounds__(256) void bn_kernel(float* __restrict__ z, int n4)
{
    int stride = gridDim.x * blockDim.x;
    for (int i = blockIdx.x * blockDim.x + threadIdx.x; i < n4; i += stride) {
        float4 v = ((const float4*)z)[i];
        int c = (i * 4) & (DIM - 1);
        float y0 = v.x * g_scale[c+0] + g_shift[c+0];
        float y1 = v.y * g_scale[c+1] + g_shift[c+1];
        float y2 = v.z * g_scale[c+2] + g_shift[c+2];
        float y3 = v.w * g_scale[c+3] + g_shift[c+3];
        y0 = (y0 >= 0.f) ? y0 : 0.2f * y0;
        y1 = (y1 >= 0.f) ? y1 : 0.2f * y1;
        y2 = (y2 >= 0.f) ? y2 : 0.2f * y2;
        y3 = (y3 >= 0.f) ? y3 : 0.2f * y3;
        ((float4*)z)[i] = make_float4(y0, y1, y2, y3);
    }
}

// ============================================================
// Launch
// ============================================================
extern "C" void kernel_launch(void* const* d_in, const int* in_sizes, int n_in,
                              void* d_out, int out_size)
{
    const float* x      = (const float*)d_in[0];
    const float* verts  = (const float*)d_in[1];
    const float* conv_w = (const float*)d_in[2];
    const float* conv_b = (const float*)d_in[3];
    const float* r_w1   = (const float*)d_in[4];
    const float* r_b1   = (const float*)d_in[5];
    const float* r_w2   = (const float*)d_in[6];
    const float* r_b2   = (const float*)d_in[7];
    const float* lin_w  = (const float*)d_in[8];
    const float* lin_b  = (const float*)d_in[9];
    const float* bn_g   = (const float*)d_in[10];
    const float* bn_b   = (const float*)d_in[11];
    float* out = (float*)d_out;

    int rows = in_sizes[0] / IMG_ELEMS;   // B*VIEWS = 16384

    cudaFuncSetAttribute(gemm_kernel, cudaFuncAttributeMaxDynamicSharedMemorySize, GEMM_SMEM);

    prep_kernel<<<1, 256>>>(verts, r_w1, r_b1, r_w2, r_b2);
    conv_kernel<<<rows, 256>>>(x, conv_w, conv_b);
    convw_kernel<<<DIM / 2, 256>>>(lin_w);
    gather_kernel<<<rows / 2, 256>>>(rows);
    gemm_kernel<<<dim3(DIM / 128, rows / 128), 256, GEMM_SMEM>>>(lin_b, out, rows);
    stats_kernel<<<rows / 64, 256>>>(out);
    finalize_kernel<<<(DIM + 255) / 256, 256>>>(bn_g, bn_b, 1.0f / (float)rows);
    bn_kernel<<<2048, 256>>>(out, rows * DIM / 4);
}

// round 16
// speedup vs baseline: 1.4593x; 1.1374x over previous
#include <cuda_runtime.h>
#include <cuda_bf16.h>
#include <math.h>
#include <stdint.h>

#define VIEWS 32
#define KNN 5
#define DIM 1024
#define MAXROWS 16384
#define IMG_ELEMS (3*34*34)   // 3468
#define NCHUNK 16             // K chunks of 64 bf16 (128B)
#define NSTAGE 3

// ---------------- static device scratch (no allocation allowed) ----------------
__device__ float g_F [(size_t)MAXROWS * DIM];                       // conv features (fp32)
__device__ __align__(1024) unsigned char g_Ahi[(size_t)NCHUNK * MAXROWS * 128];  // 32MB
__device__ __align__(1024) unsigned char g_Alo[(size_t)NCHUNK * MAXROWS * 128];  // 32MB
__device__ __align__(1024) unsigned char g_Bhi[(size_t)NCHUNK * DIM * 128];      // 2MB
__device__ __align__(1024) unsigned char g_Blo[(size_t)NCHUNK * DIM * 128];      // 2MB
__device__ int   g_idx[VIEWS * KNN];
__device__ float g_e  [VIEWS * KNN];
__device__ float g_sum  [DIM];
__device__ float g_sumsq[DIM];
__device__ float g_scale[DIM];
__device__ float g_shift[DIM];

// ---------------- PTX helpers (portable to plain sm_103 target) ----------------
__device__ __forceinline__ uint32_t smem_u32(const void* p) {
    uint32_t a;
    asm("{ .reg .u64 t; cvta.to.shared.u64 t, %1; cvt.u32.u64 %0, t; }" : "=r"(a) : "l"(p));
    return a;
}

#define MBARRIER_INIT(addr, cnt) \
    asm volatile("mbarrier.init.shared.b64 [%0], %1;" :: "r"((uint32_t)(addr)), "r"((uint32_t)(cnt)) : "memory")

#define MBARRIER_EXPECT_TX(addr, bytes) \
    asm volatile("mbarrier.arrive.expect_tx.shared.b64 _, [%0], %1;" :: "r"((uint32_t)(addr)), "r"((uint32_t)(bytes)) : "memory")

#define MBARRIER_WAIT_PARITY(mbar_addr, parity) do { \
    uint32_t _mb = (uint32_t)(mbar_addr); uint32_t _pa = (uint32_t)(parity); uint32_t _dn; \
    asm volatile("{\n\t.reg .pred p;\n\tmbarrier.try_wait.parity.acquire.cta.shared::cta.b64 p, [%1], %2;\n\tselp.b32 %0, 1, 0, p;\n\t}" \
        : "=r"(_dn) : "r"(_mb), "r"(_pa) : "memory"); \
    if (!_dn) { \
        asm volatile("{\n\t.reg .pred P1;\n\tWL_%=:\n\tmbarrier.try_wait.parity.acquire.cta.shared::cta.b64 P1, [%0], %1, 0x989680;\n\t@P1 bra.uni WD_%=;\n\tbra.uni WL_%=;\n\tWD_%=:\n\t}" \
            :: "r"(_mb), "r"(_pa) : "memory"); \
    } \
} while(0)

__device__ __forceinline__ void bulk_g2s(uint32_t dst, const void* src, uint32_t bytes, uint32_t mbar) {
    asm volatile("cp.async.bulk.shared::cta.global.mbarrier::complete_tx::bytes [%0], [%1], %2, [%3];"
        :: "r"(dst), "l"(src), "r"(bytes), "r"(mbar) : "memory");
}

#define LDSM_X4(r0, r1, r2, r3, addr) \
    asm volatile("ldmatrix.sync.aligned.m8n8.x4.shared.b16 {%0,%1,%2,%3}, [%4];" \
        : "=r"(r0), "=r"(r1), "=r"(r2), "=r"(r3) : "r"(addr))

#define MMA16816(d, a0, a1, a2, a3, b0, b1) \
    asm volatile("mma.sync.aligned.m16n8k16.row.col.f32.bf16.bf16.f32 " \
        "{%0,%1,%2,%3},{%4,%5,%6,%7},{%8,%9},{%0,%1,%2,%3};" \
        : "+f"((d)[0]), "+f"((d)[1]), "+f"((d)[2]), "+f"((d)[3]) \
        : "r"(a0), "r"(a1), "r"(a2), "r"(a3), "r"(b0), "r"(b1))

// hi/lo bf16 split helpers
__device__ __forceinline__ void split_pack(const float* a, uint32_t* hi, uint32_t* lo) {
    #pragma unroll
    for (int j = 0; j < 4; j++) {
        float f0 = a[2*j], f1 = a[2*j+1];
        __nv_bfloat16 h0 = __float2bfloat16(f0);
        __nv_bfloat16 h1 = __float2bfloat16(f1);
        float r0 = f0 - __bfloat162float(h0);
        float r1 = f1 - __bfloat162float(h1);
        __nv_bfloat16 l0 = __float2bfloat16(r0);
        __nv_bfloat16 l1 = __float2bfloat16(r1);
        hi[j] = (uint32_t)__bfloat16_as_ushort(h0) | ((uint32_t)__bfloat16_as_ushort(h1) << 16);
        lo[j] = (uint32_t)__bfloat16_as_ushort(l0) | ((uint32_t)__bfloat16_as_ushort(l1) << 16);
    }
}

// ============================================================
// Kernel 1: batch-invariant prep (kNN + relation MLP + zero stats)
// ============================================================
__global__ void prep_kernel(const float* __restrict__ verts,
                            const float* __restrict__ r_w1, const float* __restrict__ r_b1,
                            const float* __restrict__ r_w2, const float* __restrict__ r_b2)
{
    __shared__ float sv[VIEWS * 3];
    __shared__ float sd2[VIEWS * VIEWS];
    __shared__ int   sidx[VIEWS * KNN];
    int tid = threadIdx.x;

    if (tid < VIEWS * 3) sv[tid] = verts[tid];
    for (int i = tid; i < DIM; i += blockDim.x) { g_sum[i] = 0.f; g_sumsq[i] = 0.f; }
    __syncthreads();

    for (int t = tid; t < VIEWS * VIEWS; t += blockDim.x) {
        int n = t / VIEWS, m = t % VIEWS;
        float dx = sv[n*3+0] - sv[m*3+0];
        float dy = sv[n*3+1] - sv[m*3+1];
        float dz = sv[n*3+2] - sv[m*3+2];
        sd2[t] = dx*dx + dy*dy + dz*dz;
    }
    __syncthreads();

    if (tid < VIEWS) {
        unsigned used = 0u;
        for (int k = 0; k < KNN; k++) {
            float bd = 3.4e38f; int bi = 0;
            for (int m = 0; m < VIEWS; m++) {
                if (used & (1u << m)) continue;
                float dd = sd2[tid * VIEWS + m];
                if (dd < bd) { bd = dd; bi = m; }
            }
            used |= 1u << bi;
            sidx[tid * KNN + k] = bi;
            g_idx[tid * KNN + k] = bi;
        }
    }
    __syncthreads();

    if (tid < VIEWS * KNN) {
        int n = tid / KNN, k = tid % KNN;
        int i0 = sidx[n * KNN + 0];
        int ik = sidx[n * KNN + k];
        float v0x = sv[i0*3+0], v0y = sv[i0*3+1], v0z = sv[i0*3+2];
        float vkx = sv[ik*3+0], vky = sv[ik*3+1], vkz = sv[ik*3+2];
        float dvx = v0x - vkx, dvy = v0y - vky, dvz = v0z - vkz;
        float dn = sqrtf(dvx*dvx + dvy*dvy + dvz*dvz + 1e-12f);
        float vF[10] = {v0x, v0y, v0z, vkx, vky, vkz, dvx, dvy, dvz, dn};
        float e = r_b2[0];
        #pragma unroll
        for (int j = 0; j < 10; j++) {
            float a = r_b1[j];
            #pragma unroll
            for (int i = 0; i < 10; i++) a += vF[i] * r_w1[j*10 + i];
            e += fmaxf(a, 0.f) * r_w2[j];
        }
        g_e[tid] = e;
    }
}

// ============================================================
// Kernel 2: Conv2d(3->1, 3x3 valid). One block per image.
// Register-blocked: each thread computes 4 consecutive x outputs.
// ============================================================
__global__ __launch_bounds__(256) void conv_kernel(const float* __restrict__ x,
                                                   const float* __restrict__ w,
                                                   const float* __restrict__ b)
{
    __shared__ float sx[IMG_ELEMS];
    __shared__ float sw[27];
    __shared__ float sb;
    int img = blockIdx.x;
    const float* xp = x + (size_t)img * IMG_ELEMS;
    for (int i = threadIdx.x; i < IMG_ELEMS; i += 256) sx[i] = xp[i];
    if (threadIdx.x < 27) sw[threadIdx.x] = w[threadIdx.x];
    if (threadIdx.x == 0) sb = b[0];
    __syncthreads();

    int oy  = threadIdx.x >> 3;          // 0..31
    int ox4 = (threadIdx.x & 7) * 4;     // 0,4,...,28

    float acc0 = sb, acc1 = sb, acc2 = sb, acc3 = sb;
    #pragma unroll
    for (int c = 0; c < 3; c++) {
        #pragma unroll
        for (int ky = 0; ky < 3; ky++) {
            const float* rp = &sx[c*1156 + (oy+ky)*34 + ox4];
            float v0 = rp[0], v1 = rp[1], v2 = rp[2], v3 = rp[3], v4 = rp[4], v5 = rp[5];
            float w0 = sw[c*9 + ky*3 + 0], w1 = sw[c*9 + ky*3 + 1], w2 = sw[c*9 + ky*3 + 2];
            acc0 += v0*w0 + v1*w1 + v2*w2;
            acc1 += v1*w0 + v2*w1 + v3*w2;
            acc2 += v2*w0 + v3*w1 + v4*w2;
            acc3 += v3*w0 + v4*w1 + v5*w2;
        }
    }
    float4* out = (float4*)(g_F + (size_t)img * DIM + oy * 32 + ox4);
    *out = make_float4(acc0, acc1, acc2, acc3);
}

// ============================================================
// Kernel 3: gather + bf16 hi/lo split, written pre-swizzled
// into chunk-blocked layout: [chunk][row][128B], 16B unit uu
// stored at position (uu ^ (row&7)).
// ============================================================
__global__ __launch_bounds__(256) void gather_kernel(int rows)
{
    int t = threadIdx.x;
    int r = blockIdx.x * 2 + (t >> 7);
    int u = t & 127;
    int c = u >> 3, uu = u & 7;
    int n = r & (VIEWS - 1), b = r >> 5;

    float e[KNN]; int id[KNN];
    #pragma unroll
    for (int k = 0; k < KNN; k++) { e[k] = g_e[n*KNN+k]; id[k] = g_idx[n*KNN+k]; }

    float acc[8];
    #pragma unroll
    for (int j = 0; j < 8; j++) acc[j] = 0.f;

    const float* base = g_F + ((size_t)b << 5) * DIM + c * 64 + uu * 8;
    #pragma unroll
    for (int k = 0; k < KNN; k++) {
        const float4* p = (const float4*)(base + (size_t)id[k] * DIM);
        float4 v0 = p[0], v1 = p[1];
        float ek = e[k];
        acc[0] += ek*v0.x; acc[1] += ek*v0.y; acc[2] += ek*v0.z; acc[3] += ek*v0.w;
        acc[4] += ek*v1.x; acc[5] += ek*v1.y; acc[6] += ek*v1.z; acc[7] += ek*v1.w;
    }

    uint32_t hi[4], lo[4];
    split_pack(acc, hi, lo);

    size_t off = ((size_t)c * rows + r) * 128 + (size_t)((uu ^ (r & 7)) << 4);
    *(uint4*)(g_Ahi + off) = make_uint4(hi[0], hi[1], hi[2], hi[3]);
    *(uint4*)(g_Alo + off) = make_uint4(lo[0], lo[1], lo[2], lo[3]);
}

// ============================================================
// Kernel 4: convert W (1024x1024 fp32, [n][k]) to bf16 hi/lo,
// pre-swizzled chunk-blocked.
// ============================================================
__global__ __launch_bounds__(256) void convw_kernel(const float* __restrict__ W)
{
    int t = threadIdx.x;
    int r = blockIdx.x * 2 + (t >> 7);
    int u = t & 127;
    int c = u >> 3, uu = u & 7;

    const float4* p = (const float4*)(W + (size_t)r * DIM + c * 64 + uu * 8);
    float4 v0 = p[0], v1 = p[1];
    float a[8] = {v0.x, v0.y, v0.z, v0.w, v1.x, v1.y, v1.z, v1.w};

    uint32_t hi[4], lo[4];
    split_pack(a, hi, lo);

    size_t off = ((size_t)c * DIM + r) * 128 + (size_t)((uu ^ (r & 7)) << 4);
    *(uint4*)(g_Bhi + off) = make_uint4(hi[0], hi[1], hi[2], hi[3]);
    *(uint4*)(g_Blo + off) = make_uint4(lo[0], lo[1], lo[2], lo[3]);
}

// ============================================================
// Kernel 5: mma.sync bf16 GEMM  z = Fa @ W^T + bias.
// CTA tile 128x128, K-chunk 64, 3-stage cp.async.bulk pipeline.
// 8 warps as 2(M) x 4(N); warp tile 64x32; m16n8k16 bf16 MMA.
// 3-pass split, pass-major ordering (dep distance 16 MMAs).
// ============================================================
#define STAGE_BYTES 65536   // Ahi 16K | Alo 16K | Bhi 16K | Blo 16K
#define GEMM_SMEM (NSTAGE * STAGE_BYTES)

__global__ void __launch_bounds__(256, 1) gemm_kernel(const float* __restrict__ lin_b,
                                                      float* __restrict__ z, int rows)
{
    extern __shared__ __align__(1024) unsigned char smem[];
    __shared__ uint64_t mbar_store[NSTAGE];
    uint32_t sbase = smem_u32(smem);
    uint32_t mb = smem_u32(mbar_store);

    int tid = threadIdx.x;
    int wid = tid >> 5, lane = tid & 31;
    int wm = wid >> 2;        // 0..1  (M half, 64 rows)
    int wn = wid & 3;         // 0..3  (N quarter, 32 cols)

    int m0 = blockIdx.y * 128;
    int n0 = blockIdx.x * 128;

    if (tid == 0) {
        #pragma unroll
        for (int s = 0; s < NSTAGE; s++) MBARRIER_INIT(mb + s * 8, 1);
        asm volatile("fence.proxy.async.shared::cta;" ::: "memory");
    }
    __syncthreads();

    // prologue: stage chunks 0..NSTAGE-1
    if (tid == 0) {
        #pragma unroll
        for (int c = 0; c < NSTAGE; c++) {
            uint32_t fullb = mb + c * 8;
            MBARRIER_EXPECT_TX(fullb, (uint32_t)STAGE_BYTES);
            uint32_t base = sbase + c * STAGE_BYTES;
            size_t aoff = ((size_t)c * rows + m0) * 128;
            size_t boff = ((size_t)c * DIM + n0) * 128;
            bulk_g2s(base,          g_Ahi + aoff, 16384, fullb);
            bulk_g2s(base + 16384,  g_Alo + aoff, 16384, fullb);
            bulk_g2s(base + 32768,  g_Bhi + boff, 16384, fullb);
            bulk_g2s(base + 49152,  g_Blo + boff, 16384, fullb);
        }
    }

    // per-thread ldmatrix addressing
    int lrow8 = (lane & 7) + ((lane >> 3) & 1) * 8;  // 0..15 row within 16-row tile
    int ksel  = lane >> 4;                            // 0/1: k-seg select within k16

    uint32_t a_rowoff[4]; int a_sw[4];
    #pragma unroll
    for (int mt = 0; mt < 4; mt++) {
        int rw = wm * 64 + mt * 16 + lrow8;
        a_rowoff[mt] = (uint32_t)rw * 128;
        a_sw[mt] = rw & 7;
    }
    uint32_t b_rowoff[2]; int b_sw[2];
    #pragma unroll
    for (int np = 0; np < 2; np++) {
        int rw = wn * 32 + np * 16 + lrow8;
        b_rowoff[np] = (uint32_t)rw * 128;
        b_sw[np] = rw & 7;
    }

    float acc[4][4][4];
    #pragma unroll
    for (int mt = 0; mt < 4; mt++)
        #pragma unroll
        for (int nt = 0; nt < 4; nt++)
            #pragma unroll
            for (int j = 0; j < 4; j++) acc[mt][nt][j] = 0.f;

    int s = 0, ph = 0;
    for (int c = 0; c < NCHUNK; c++) {
        MBARRIER_WAIT_PARITY(mb + s * 8, ph);

        uint32_t stA  = sbase + s * STAGE_BYTES;
        uint32_t stAl = stA + 16384;
        uint32_t stB  = stA + 32768;
        uint32_t stBl = stA + 49152;

        #pragma unroll
        for (int kk = 0; kk < 4; kk++) {
            int kseg = (kk << 1) | ksel;
            uint32_t ah[4][4], al[4][4], bh[2][4], bl[2][4];
            #pragma unroll
            for (int mt = 0; mt < 4; mt++) {
                uint32_t offa = a_rowoff[mt] + (uint32_t)((kseg ^ a_sw[mt]) << 4);
                LDSM_X4(ah[mt][0], ah[mt][1], ah[mt][2], ah[mt][3], stA  + offa);
                LDSM_X4(al[mt][0], al[mt][1], al[mt][2], al[mt][3], stAl + offa);
            }
            #pragma unroll
            for (int np = 0; np < 2; np++) {
                uint32_t offb = b_rowoff[np] + (uint32_t)((kseg ^ b_sw[np]) << 4);
                LDSM_X4(bh[np][0], bh[np][1], bh[np][2], bh[np][3], stB  + offb);
                LDSM_X4(bl[np][0], bl[np][1], bl[np][2], bl[np][3], stBl + offb);
            }
            // pass 1: Ahi * Bhi  (16 independent accumulators)
            #pragma unroll
            for (int mt = 0; mt < 4; mt++)
                #pragma unroll
                for (int nt = 0; nt < 4; nt++) {
                    int np = nt >> 1, sel = nt & 1;
                    MMA16816(acc[mt][nt], ah[mt][0], ah[mt][1], ah[mt][2], ah[mt][3],
                             bh[np][sel], bh[np][sel + 2]);
                }
            // pass 2: Ahi * Blo
            #pragma unroll
            for (int mt = 0; mt < 4; mt++)
                #pragma unroll
                for (int nt = 0; nt < 4; nt++) {
                    int np = nt >> 1, sel = nt & 1;
                    MMA16816(acc[mt][nt], ah[mt][0], ah[mt][1], ah[mt][2], ah[mt][3],
                             bl[np][sel], bl[np][sel + 2]);
                }
            // pass 3: Alo * Bhi
            #pragma unroll
            for (int mt = 0; mt < 4; mt++)
                #pragma unroll
                for (int nt = 0; nt < 4; nt++) {
                    int np = nt >> 1, sel = nt & 1;
                    MMA16816(acc[mt][nt], al[mt][0], al[mt][1], al[mt][2], al[mt][3],
                             bh[np][sel], bh[np][sel + 2]);
                }
        }

        __syncthreads();   // all warps done reading stage s
        if (tid == 0 && c + NSTAGE < NCHUNK) {
            int cn = c + NSTAGE;
            uint32_t fullb = mb + s * 8;
            MBARRIER_EXPECT_TX(fullb, (uint32_t)STAGE_BYTES);
            uint32_t base = sbase + s * STAGE_BYTES;
            size_t aoff = ((size_t)cn * rows + m0) * 128;
            size_t boff = ((size_t)cn * DIM + n0) * 128;
            bulk_g2s(base,          g_Ahi + aoff, 16384, fullb);
            bulk_g2s(base + 16384,  g_Alo + aoff, 16384, fullb);
            bulk_g2s(base + 32768,  g_Bhi + boff, 16384, fullb);
            bulk_g2s(base + 49152,  g_Blo + boff, 16384, fullb);
        }
        if (++s == NSTAGE) { s = 0; ph ^= 1; }
    }

    // epilogue: acc -> z + bias
    int qr = lane >> 2;          // 0..7
    int qc = (lane & 3) * 2;     // 0,2,4,6
    #pragma unroll
    for (int nt = 0; nt < 4; nt++) {
        int cb = n0 + wn * 32 + nt * 8 + qc;
        float b0 = __ldg(lin_b + cb);
        float b1 = __ldg(lin_b + cb + 1);
        #pragma unroll
        for (int mt = 0; mt < 4; mt++) {
            int mr = m0 + wm * 64 + mt * 16 + qr;
            float2* p0 = (float2*)(z + (size_t)mr * DIM + cb);
            float2* p1 = (float2*)(z + (size_t)(mr + 8) * DIM + cb);
            *p0 = make_float2(acc[mt][nt][0] + b0, acc[mt][nt][1] + b1);
            *p1 = make_float2(acc[mt][nt][2] + b0, acc[mt][nt][3] + b1);
        }
    }
}

// ============================================================
// Kernel 6: per-column sum / sumsq over z (float4 loads)
// ============================================================
__global__ __launch_bounds__(256) void stats_kernel(const float* __restrict__ z)
{
    int t = threadIdx.x;
    int r0 = blockIdx.x * 64;
    float s[4] = {0.f, 0.f, 0.f, 0.f};
    float q[4] = {0.f, 0.f, 0.f, 0.f};
    const float4* zp = (const float4*)(z + (size_t)r0 * DIM) + t;
    for (int r = 0; r < 64; r++) {
        float4 v = zp[(size_t)r * (DIM / 4)];
        s[0] += v.x; q[0] += v.x * v.x;
        s[1] += v.y; q[1] += v.y * v.y;
        s[2] += v.z; q[2] += v.z * v.z;
        s[3] += v.w; q[3] += v.w * v.w;
    }
    int c = t * 4;
    #pragma unroll
    for (int j = 0; j < 4; j++) {
        atomicAdd(&g_sum[c + j], s[j]);
        atomicAdd(&g_sumsq[c + j], q[j]);
    }
}

// ============================================================
// Kernel 7: finalize BN coefficients
// ============================================================
__global__ void finalize_kernel(const float* __restrict__ bn_g,
                                const float* __restrict__ bn_b, float invN)
{
    int d = blockIdx.x * blockDim.x + threadIdx.x;
    if (d < DIM) {
        float mean = g_sum[d] * invN;
        float var  = g_sumsq[d] * invN - mean * mean;
        float istd = rsqrtf(var + 1e-5f);
        float a = istd * bn_g[d];
        g_scale[d] = a;
        g_shift[d] = bn_b[d] - mean * a;
    }
}

// ============================================================
// Kernel 8: BN apply + leaky relu in place
// ============================================================
__global__ __launch_bounds__(256) void bn_kernel(float* __restrict__ z, int n4)
{
    int stride = gridDim.x * blockDim.x;
    for (int i = blockIdx.x * blockDim.x + threadIdx.x; i < n4; i += stride) {
        float4 v = ((const float4*)z)[i];
        int c = (i * 4) & (DIM - 1);
        float y0 = v.x * g_scale[c+0] + g_shift[c+0];
        float y1 = v.y * g_scale[c+1] + g_shift[c+1];
        float y2 = v.z * g_scale[c+2] + g_shift[c+2];
        float y3 = v.w * g_scale[c+3] + g_shift[c+3];
        y0 = (y0 >= 0.f) ? y0 : 0.2f * y0;
        y1 = (y1 >= 0.f) ? y1 : 0.2f * y1;
        y2 = (y2 >= 0.f) ? y2 : 0.2f * y2;
        y3 = (y3 >= 0.f) ? y3 : 0.2f * y3;
        ((float4*)z)[i] = make_float4(y0, y1, y2, y3);
    }
}

// ============================================================
// Launch
// ============================================================
extern "C" void kernel_launch(void* const* d_in, const int* in_sizes, int n_in,
                              void* d_out, int out_size)
{
    const float* x      = (const float*)d_in[0];
    const float* verts  = (const float*)d_in[1];
    const float* conv_w = (const float*)d_in[2];
    const float* conv_b = (const float*)d_in[3];
    const float* r_w1   = (const float*)d_in[4];
    const float* r_b1   = (const float*)d_in[5];
    const float* r_w2   = (const float*)d_in[6];
    const float* r_b2   = (const float*)d_in[7];
    const float* lin_w  = (const float*)d_in[8];
    const float* lin_b  = (const float*)d_in[9];
    const float* bn_g   = (const float*)d_in[10];
    const float* bn_b   = (const float*)d_in[11];
    float* out = (float*)d_out;

    int rows = in_sizes[0] / IMG_ELEMS;   // B*VIEWS = 16384

    cudaFuncSetAttribute(gemm_kernel, cudaFuncAttributeMaxDynamicSharedMemorySize, GEMM_SMEM);

    prep_kernel<<<1, 256>>>(verts, r_w1, r_b1, r_w2, r_b2);
    conv_kernel<<<rows, 256>>>(x, conv_w, conv_b);
    convw_kernel<<<DIM / 2, 256>>>(lin_w);
    gather_kernel<<<rows / 2, 256>>>(rows);
    gemm_kernel<<<dim3(DIM / 128, rows / 128), 256, GEMM_SMEM>>>(lin_b, out, rows);
    stats_kernel<<<rows / 64, 256>>>(out);
    finalize_kernel<<<(DIM + 255) / 256, 256>>>(bn_g, bn_b, 1.0f / (float)rows);
    bn_kernel<<<2048, 256>>>(out, rows * DIM / 4);
}